// round 2
// baseline (speedup 1.0000x reference)
#include <cuda_runtime.h>
#include <math.h>

#define BB    128
#define TT    1024
#define IND   256
#define HH    512
#define NH    1024          // 2*H
#define FC1N  2048
#define OUTN  128
#define EPSF  1e-5f

#define M_BIG (TT * BB)
#define NCTA  128           // persistent recurrence grid
#define SROW  130           // smem row stride in float4 (520 floats)
#define RNN_SMEM ((16 + 64) * SROW * 16)   // 166,400 bytes

// ---------------- device scratch ----------------
__device__ float g_P[TT * BB * NH];      // 512 MB: P0 then P1
__device__ float g_H0buf[TT * BB * NH];  // 512 MB: all layer-0 hidden states
__device__ float g_hi0[BB * NH];
__device__ float g_hi1[BB * NH];
__device__ float g_h1a[BB * NH];
__device__ float g_h1b[BB * NH];
__device__ float g_bias0[NH];
__device__ float g_bias1[NH];
__device__ float g_y1[BB * NH];
__device__ float g_z[BB * FC1N];
__device__ int   g_ctr0[TT];             // per-step barrier counters, layer 0
__device__ int   g_ctr1[TT];             // per-step barrier counters, layer 1

// ---------------- setup: fold biases, pack initial states, zero barriers ----------------
__global__ void setup_kernel(const float* __restrict__ h0,
                             const float* __restrict__ bih0, const float* __restrict__ bhh0,
                             const float* __restrict__ bih1, const float* __restrict__ bhh1)
{
    int i0 = blockIdx.x * blockDim.x + threadIdx.x;
    if (i0 < NH) {
        g_bias0[i0] = bih0[i0] + bhh0[i0];
        g_bias1[i0] = bih1[i0] + bhh1[i0];
    }
    if (i0 < TT) { g_ctr0[i0] = 0; g_ctr1[i0] = 0; }
    int stride = gridDim.x * blockDim.x;
    for (int idx = i0; idx < BB * NH; idx += stride) {
        int b = idx >> 10;
        int n = idx & (NH - 1);
        int d = n >> 9;
        int j = n & (HH - 1);
        g_hi0[idx] = h0[(size_t)(d * BB + b) * HH + j];
        g_hi1[idx] = h0[(size_t)((2 + d) * BB + b) * HH + j];
    }
}

// ---------------- generic fp32 GEMM:  C[M,N] = A[M,K] * W[N,K]^T + bias ----------------
template<int AMODE, int ACT>
__global__ void __launch_bounds__(256) gemm_bias(
    const float* __restrict__ A, const float* __restrict__ W,
    const float* __restrict__ bias, float* __restrict__ C,
    int M, int N, int K)
{
    __shared__ float sA[16][68];
    __shared__ float sB[16][68];
    const int m0  = blockIdx.y * 64;
    const int n0  = blockIdx.x * 64;
    const int tid = threadIdx.x;
    const int lk  = tid & 15;
    const int lr  = tid >> 4;
    const int tx  = tid & 15;
    const int ty  = tid >> 4;

    float acc[4][4];
#pragma unroll
    for (int i = 0; i < 4; i++)
#pragma unroll
        for (int j = 0; j < 4; j++) acc[i][j] = 0.f;

    for (int k0 = 0; k0 < K; k0 += 16) {
#pragma unroll
        for (int r = 0; r < 4; r++) {
            int m = m0 + lr + r * 16;
            const float* arow;
            if (AMODE == 1) arow = A + ((size_t)((m & (BB - 1)) * TT + (m >> 7))) * K;
            else            arow = A + (size_t)m * K;
            sA[lk][lr + r * 16] = arow[k0 + lk];
            sB[lk][lr + r * 16] = W[(size_t)(n0 + lr + r * 16) * K + k0 + lk];
        }
        __syncthreads();
#pragma unroll
        for (int kk = 0; kk < 16; kk++) {
            float4 a4 = *(const float4*)&sA[kk][tx * 4];
            float4 b4 = *(const float4*)&sB[kk][ty * 4];
            float av[4] = {a4.x, a4.y, a4.z, a4.w};
            float bv[4] = {b4.x, b4.y, b4.z, b4.w};
#pragma unroll
            for (int i = 0; i < 4; i++)
#pragma unroll
                for (int j = 0; j < 4; j++) acc[i][j] += av[i] * bv[j];
        }
        __syncthreads();
    }

#pragma unroll
    for (int i = 0; i < 4; i++) {
        int m = m0 + tx * 4 + i;
        float4 v;
        float* vp = (float*)&v;
#pragma unroll
        for (int j = 0; j < 4; j++) {
            float t = acc[i][j] + bias[n0 + ty * 4 + j];
            if (ACT == 2) t = 1.f / (1.f + expf(-t));
            vp[j] = t;
        }
        *(float4*)&C[(size_t)m * N + n0 + ty * 4] = v;
    }
}

// ---------------- persistent recurrence: one kernel runs all TT steps ----------------
// 128 CTAs x 128 threads, 1 CTA/SM. CTA tile: 64 b x 16 n; thread: 4b x 2n.
// sW (16 x 512 f) resident across all steps; sH staged per step via __ldcg.
// Grid barrier per step via per-step atomic counters (zeroed by setup_kernel).
template<int LAYER0>
__global__ void __launch_bounds__(128, 1) rnn_layer(
    const float* __restrict__ P, const float* __restrict__ hinit,
    const float* __restrict__ Whh, float* __restrict__ Hbuf,
    float* __restrict__ pA, float* __restrict__ pB, int* __restrict__ ctr)
{
    extern __shared__ float smem[];
    float4* sW4 = (float4*)smem;                 // [16][SROW]
    float4* sH4 = ((float4*)smem) + 16 * SROW;   // [64][SROW]

    const int tid   = threadIdx.x;
    const int bid   = blockIdx.x;
    const int nt    = bid & 63;
    const int bt    = bid >> 6;
    const int nBase = nt * 16;
    const int b0    = bt * 64;
    const int kOff4 = (nBase >= HH) ? (HH >> 2) : 0;   // float4 offset into Hin row
    const int tx    = tid & 15;     // b-group
    const int ty    = tid >> 4;     // n-group (0..7)

    // load this CTA's 16 Whh rows once (rows are [NH][HH], 128 float4 each)
    const float4* W4 = (const float4*)Whh;
#pragma unroll
    for (int n = 0; n < 16; n++)
        sW4[n * SROW + tid] = W4[(size_t)(nBase + n) * 128 + tid];
    __syncthreads();

    for (int t = 0; t < TT; t++) {
        const float* Hin;
        float* Hout;
        if (LAYER0) {
            Hin  = (t == 0) ? hinit : (Hbuf + (size_t)(t - 1) * BB * NH);
            Hout = Hbuf + (size_t)t * BB * NH;
        } else {
            Hin  = (t == 0) ? hinit : (((t - 1) & 1) ? pB : pA);
            Hout = (t & 1) ? pB : pA;
        }

        // stage Hin tile: 64 rows x 128 float4 (this CTA's direction slice)
        const float4* Hin4 = (const float4*)Hin;
#pragma unroll 8
        for (int b = 0; b < 64; b++)
            sH4[b * SROW + tid] = __ldcg(&Hin4[(size_t)(b0 + b) * 256 + kOff4 + tid]);
        __syncthreads();

        float acc[4][2];
#pragma unroll
        for (int i = 0; i < 4; i++) { acc[i][0] = 0.f; acc[i][1] = 0.f; }

        const float4* w0p = &sW4[(ty * 2) * SROW];
        const float4* w1p = &sW4[(ty * 2 + 1) * SROW];
#pragma unroll 2
        for (int kq = 0; kq < 128; kq++) {
            float4 w0 = w0p[kq];
            float4 w1 = w1p[kq];
#pragma unroll
            for (int i = 0; i < 4; i++) {
                float4 a = sH4[(tx * 4 + i) * SROW + kq];
                acc[i][0] += a.x * w0.x; acc[i][0] += a.y * w0.y;
                acc[i][0] += a.z * w0.z; acc[i][0] += a.w * w0.w;
                acc[i][1] += a.x * w1.x; acc[i][1] += a.y * w1.y;
                acc[i][1] += a.z * w1.z; acc[i][1] += a.w * w1.w;
            }
        }

        // epilogue: add P, relu, store (bypass L1 so peers see fresh data)
        const float* Pt = P + (size_t)t * BB * NH;
        const int n = nBase + ty * 2;
#pragma unroll
        for (int i = 0; i < 4; i++) {
            int b = b0 + tx * 4 + i;
            float2 p = *(const float2*)&Pt[(size_t)b * NH + n];
            float2 o;
            o.x = fmaxf(acc[i][0] + p.x, 0.f);
            o.y = fmaxf(acc[i][1] + p.y, 0.f);
            __stcg((float2*)&Hout[(size_t)b * NH + n], o);
        }

        __syncthreads();           // everyone done reading sH before next stage
        __threadfence();           // make stores visible before arrival
        if (tid == 0) {
            atomicAdd(&ctr[t], 1);
            while (((volatile int*)ctr)[t] < NCTA) __nanosleep(64);
        }
        __syncthreads();
        __threadfence();           // acquire: subsequent __ldcg sees peer stores
    }
}

// ---------------- BatchNorm1d (training, biased var) + ReLU ----------------
__global__ void bn_relu(const float* __restrict__ V, const float* __restrict__ gw,
                        const float* __restrict__ bw, float* __restrict__ Y, int cols)
{
    int c = blockIdx.x;
    int t = threadIdx.x;
    float v = V[(size_t)t * cols + c];
    float s = v, ss = v * v;
#pragma unroll
    for (int o = 16; o > 0; o >>= 1) {
        s  += __shfl_down_sync(0xffffffffu, s,  o);
        ss += __shfl_down_sync(0xffffffffu, ss, o);
    }
    __shared__ float rs[4], rq[4];
    if ((t & 31) == 0) { rs[t >> 5] = s; rq[t >> 5] = ss; }
    __syncthreads();
    float S = rs[0] + rs[1] + rs[2] + rs[3];
    float Q = rq[0] + rq[1] + rq[2] + rq[3];
    float mean = S * (1.f / BB);
    float var  = Q * (1.f / BB) - mean * mean;
    float y = (v - mean) * rsqrtf(var + EPSF) * gw[c] + bw[c];
    Y[(size_t)t * cols + c] = fmaxf(y, 0.f);
}

// ---------------- launch ----------------
extern "C" void kernel_launch(void* const* d_in, const int* in_sizes, int n_in,
                              void* d_out, int out_size)
{
    (void)in_sizes; (void)n_in; (void)out_size;
    const float* x     = (const float*)d_in[0];
    const float* h0    = (const float*)d_in[1];
    const float* W_ih0 = (const float*)d_in[2];
    const float* W_hh0 = (const float*)d_in[3];
    const float* b_ih0 = (const float*)d_in[4];
    const float* b_hh0 = (const float*)d_in[5];
    const float* W_ih1 = (const float*)d_in[6];
    const float* W_hh1 = (const float*)d_in[7];
    const float* b_ih1 = (const float*)d_in[8];
    const float* b_hh1 = (const float*)d_in[9];
    const float* bn1_g = (const float*)d_in[10];
    const float* bn1_b = (const float*)d_in[11];
    const float* fc1_W = (const float*)d_in[12];
    const float* fc1_b = (const float*)d_in[13];
    const float* bn2_g = (const float*)d_in[14];
    const float* bn2_b = (const float*)d_in[15];
    const float* fc2_W = (const float*)d_in[16];
    const float* fc2_b = (const float*)d_in[17];
    float* out = (float*)d_out;

    float *P, *H0p, *hi0, *hi1, *h1a, *h1b, *bs0, *bs1, *y1, *z;
    int *c0, *c1;
    cudaGetSymbolAddress((void**)&P,   g_P);
    cudaGetSymbolAddress((void**)&H0p, g_H0buf);
    cudaGetSymbolAddress((void**)&hi0, g_hi0);
    cudaGetSymbolAddress((void**)&hi1, g_hi1);
    cudaGetSymbolAddress((void**)&h1a, g_h1a);
    cudaGetSymbolAddress((void**)&h1b, g_h1b);
    cudaGetSymbolAddress((void**)&bs0, g_bias0);
    cudaGetSymbolAddress((void**)&bs1, g_bias1);
    cudaGetSymbolAddress((void**)&y1,  g_y1);
    cudaGetSymbolAddress((void**)&z,   g_z);
    cudaGetSymbolAddress((void**)&c0,  g_ctr0);
    cudaGetSymbolAddress((void**)&c1,  g_ctr1);

    cudaFuncSetAttribute(rnn_layer<1>, cudaFuncAttributeMaxDynamicSharedMemorySize, RNN_SMEM);
    cudaFuncSetAttribute(rnn_layer<0>, cudaFuncAttributeMaxDynamicSharedMemorySize, RNN_SMEM);

    // 0) biases + initial hidden + barrier counters
    setup_kernel<<<256, 256>>>(h0, b_ih0, b_hh0, b_ih1, b_hh1);

    // 1) P0 = x @ Wih0^T + biases   (34.4 GMAC)
    gemm_bias<1, 0><<<dim3(NH / 64, M_BIG / 64), 256>>>(x, W_ih0, bs0, P, M_BIG, NH, IND);

    // 2) layer-0 recurrence, persistent (68.7 GMAC, all timesteps stored)
    rnn_layer<1><<<NCTA, 128, RNN_SMEM>>>(P, hi0, W_hh0, H0p, nullptr, nullptr, c0);

    // 3) P1 = H0 @ Wih1^T + biases  (137.4 GMAC, reuses P)
    gemm_bias<0, 0><<<dim3(NH / 64, M_BIG / 64), 256>>>(H0p, W_ih1, bs1, P, M_BIG, NH, NH);

    // 4) layer-1 recurrence, persistent; final state lands in h1b (t=1023 odd)
    rnn_layer<0><<<NCTA, 128, RNN_SMEM>>>(P, hi1, W_hh1, nullptr, h1a, h1b, c1);

    // 5) head
    bn_relu<<<NH, 128>>>(h1b, bn1_g, bn1_b, y1, NH);
    gemm_bias<0, 0><<<dim3(FC1N / 64, BB / 64), 256>>>(y1, fc1_W, fc1_b, z, BB, FC1N, NH);
    bn_relu<<<FC1N, 128>>>(z, bn2_g, bn2_b, z, FC1N);
    gemm_bias<0, 2><<<dim3(OUTN / 64, BB / 64), 256>>>(z, fc2_W, fc2_b, out, BB, OUTN, FC1N);
}

// round 3
// speedup vs baseline: 2.7822x; 2.7822x over previous
#include <cuda_runtime.h>
#include <math.h>

#define BB    128
#define TT    1024
#define IND   256
#define HH    512
#define NH    1024          // 2*H
#define FC1N  2048
#define OUTN  128
#define EPSF  1e-5f

#define M_BIG (TT * BB)
#define NCTA  128           // persistent recurrence grid
#define SROW  129           // smem row stride in float4 (odd -> bank-group step 1)
#define RNN_SMEM ((16 + 64) * SROW * 16)   // 165,120 bytes

// ---------------- device scratch ----------------
__device__ float g_P[TT * BB * NH];      // 512 MB: P0 then P1
__device__ float g_H0buf[TT * BB * NH];  // 512 MB: all layer-0 hidden states
__device__ float g_hi0[BB * NH];
__device__ float g_hi1[BB * NH];
__device__ float g_h1a[BB * NH];
__device__ float g_h1b[BB * NH];
__device__ float g_bias0[NH];
__device__ float g_bias1[NH];
__device__ float g_y1[BB * NH];
__device__ float g_z[BB * FC1N];
__device__ int   g_ctr0[TT];
__device__ int   g_ctr1[TT];

// ---------------- setup ----------------
__global__ void setup_kernel(const float* __restrict__ h0,
                             const float* __restrict__ bih0, const float* __restrict__ bhh0,
                             const float* __restrict__ bih1, const float* __restrict__ bhh1)
{
    int i0 = blockIdx.x * blockDim.x + threadIdx.x;
    if (i0 < NH) {
        g_bias0[i0] = bih0[i0] + bhh0[i0];
        g_bias1[i0] = bih1[i0] + bhh1[i0];
    }
    if (i0 < TT) { g_ctr0[i0] = 0; g_ctr1[i0] = 0; }
    int stride = gridDim.x * blockDim.x;
    for (int idx = i0; idx < BB * NH; idx += stride) {
        int b = idx >> 10;
        int n = idx & (NH - 1);
        int d = n >> 9;
        int j = n & (HH - 1);
        g_hi0[idx] = h0[(size_t)(d * BB + b) * HH + j];
        g_hi1[idx] = h0[(size_t)((2 + d) * BB + b) * HH + j];
    }
}

// ---------------- big GEMM: 128x128 tile, 8x8/thread:  C = A * W^T + bias ----------------
// AMODE 0: A row-major [M][K]. AMODE 1: A is x[B,T,IN], row m=t*B+b -> x + (b*T+t)*K.
template<int AMODE>
__global__ void __launch_bounds__(256) gemm_big(
    const float* __restrict__ A, const float* __restrict__ W,
    const float* __restrict__ bias, float* __restrict__ C,
    int M, int N, int K)
{
    __shared__ float sA[16][132];
    __shared__ float sB[16][132];
    const int m0  = blockIdx.y * 128;
    const int n0  = blockIdx.x * 128;
    const int tid = threadIdx.x;
    const int lk  = tid & 15;   // k for loads
    const int lr  = tid >> 4;   // row group (0..15)
    const int tx  = tid & 15;   // m group
    const int ty  = tid >> 4;   // n group

    float acc[8][8];
#pragma unroll
    for (int i = 0; i < 8; i++)
#pragma unroll
        for (int j = 0; j < 8; j++) acc[i][j] = 0.f;

    for (int k0 = 0; k0 < K; k0 += 16) {
#pragma unroll
        for (int r = 0; r < 8; r++) {
            int m = m0 + lr + r * 16;
            const float* arow;
            if (AMODE == 1) arow = A + ((size_t)((m & (BB - 1)) * TT + (m >> 7))) * K;
            else            arow = A + (size_t)m * K;
            sA[lk][lr + r * 16] = arow[k0 + lk];
            sB[lk][lr + r * 16] = W[(size_t)(n0 + lr + r * 16) * K + k0 + lk];
        }
        __syncthreads();
#pragma unroll
        for (int kk = 0; kk < 16; kk++) {
            float4 a0 = *(const float4*)&sA[kk][tx * 4];
            float4 a1 = *(const float4*)&sA[kk][64 + tx * 4];
            float4 b0 = *(const float4*)&sB[kk][ty * 4];
            float4 b1 = *(const float4*)&sB[kk][64 + ty * 4];
            float av[8] = {a0.x, a0.y, a0.z, a0.w, a1.x, a1.y, a1.z, a1.w};
            float bv[8] = {b0.x, b0.y, b0.z, b0.w, b1.x, b1.y, b1.z, b1.w};
#pragma unroll
            for (int i = 0; i < 8; i++)
#pragma unroll
                for (int j = 0; j < 8; j++) acc[i][j] += av[i] * bv[j];
        }
        __syncthreads();
    }

#pragma unroll
    for (int ih = 0; ih < 2; ih++)
#pragma unroll
    for (int i = 0; i < 4; i++) {
        int m = m0 + ih * 64 + tx * 4 + i;
#pragma unroll
        for (int jh = 0; jh < 2; jh++) {
            int n = n0 + jh * 64 + ty * 4;
            float4 v;
            v.x = acc[ih * 4 + i][jh * 4 + 0] + bias[n + 0];
            v.y = acc[ih * 4 + i][jh * 4 + 1] + bias[n + 1];
            v.z = acc[ih * 4 + i][jh * 4 + 2] + bias[n + 2];
            v.w = acc[ih * 4 + i][jh * 4 + 3] + bias[n + 3];
            *(float4*)&C[(size_t)m * N + n] = v;
        }
    }
}

// ---------------- small GEMM for head: 64x64 tile ----------------
template<int ACT>
__global__ void __launch_bounds__(256) gemm_bias(
    const float* __restrict__ A, const float* __restrict__ W,
    const float* __restrict__ bias, float* __restrict__ C,
    int M, int N, int K)
{
    __shared__ float sA[16][68];
    __shared__ float sB[16][68];
    const int m0  = blockIdx.y * 64;
    const int n0  = blockIdx.x * 64;
    const int tid = threadIdx.x;
    const int lk  = tid & 15;
    const int lr  = tid >> 4;
    const int tx  = tid & 15;
    const int ty  = tid >> 4;

    float acc[4][4];
#pragma unroll
    for (int i = 0; i < 4; i++)
#pragma unroll
        for (int j = 0; j < 4; j++) acc[i][j] = 0.f;

    for (int k0 = 0; k0 < K; k0 += 16) {
#pragma unroll
        for (int r = 0; r < 4; r++) {
            int m = m0 + lr + r * 16;
            sA[lk][lr + r * 16] = A[(size_t)m * K + k0 + lk];
            sB[lk][lr + r * 16] = W[(size_t)(n0 + lr + r * 16) * K + k0 + lk];
        }
        __syncthreads();
#pragma unroll
        for (int kk = 0; kk < 16; kk++) {
            float4 a4 = *(const float4*)&sA[kk][tx * 4];
            float4 b4 = *(const float4*)&sB[kk][ty * 4];
            float av[4] = {a4.x, a4.y, a4.z, a4.w};
            float bv[4] = {b4.x, b4.y, b4.z, b4.w};
#pragma unroll
            for (int i = 0; i < 4; i++)
#pragma unroll
                for (int j = 0; j < 4; j++) acc[i][j] += av[i] * bv[j];
        }
        __syncthreads();
    }

#pragma unroll
    for (int i = 0; i < 4; i++) {
        int m = m0 + tx * 4 + i;
        float4 v;
        float* vp = (float*)&v;
#pragma unroll
        for (int j = 0; j < 4; j++) {
            float t = acc[i][j] + bias[n0 + ty * 4 + j];
            if (ACT == 2) t = 1.f / (1.f + expf(-t));
            vp[j] = t;
        }
        *(float4*)&C[(size_t)m * N + n0 + ty * 4] = v;
    }
}

// ---------------- persistent recurrence ----------------
// 128 CTAs x 128 threads. CTA tile: 64 b x 16 n; thread: 4 b (tx+16i) x 2 n.
// SROW=129 float4 -> per-b-row bank-group step = 1 -> worst 2-way conflict.
template<int LAYER0>
__global__ void __launch_bounds__(128, 1) rnn_layer(
    const float* __restrict__ P, const float* __restrict__ hinit,
    const float* __restrict__ Whh, float* __restrict__ Hbuf,
    float* __restrict__ pA, float* __restrict__ pB, int* __restrict__ ctr)
{
    extern __shared__ float smem[];
    float4* sW4 = (float4*)smem;                 // [16][SROW]
    float4* sH4 = ((float4*)smem) + 16 * SROW;   // [64][SROW]

    const int tid   = threadIdx.x;
    const int bid   = blockIdx.x;
    const int nt    = bid & 63;
    const int bt    = bid >> 6;
    const int nBase = nt * 16;
    const int b0    = bt * 64;
    const int kOff4 = (nBase >= HH) ? (HH >> 2) : 0;
    const int tx    = tid & 15;     // b group (rows tx, tx+16, tx+32, tx+48)
    const int ty    = tid >> 4;     // n group (0..7)

    const float4* W4 = (const float4*)Whh;
#pragma unroll
    for (int n = 0; n < 16; n++)
        sW4[n * SROW + tid] = W4[(size_t)(nBase + n) * 128 + tid];
    __syncthreads();

    for (int t = 0; t < TT; t++) {
        const float* Hin;
        float* Hout;
        if (LAYER0) {
            Hin  = (t == 0) ? hinit : (Hbuf + (size_t)(t - 1) * BB * NH);
            Hout = Hbuf + (size_t)t * BB * NH;
        } else {
            Hin  = (t == 0) ? hinit : (((t - 1) & 1) ? pB : pA);
            Hout = (t & 1) ? pB : pA;
        }

        // stage Hin tile: 64 rows x 128 float4 (consecutive-lane writes: conflict-free)
        const float4* Hin4 = (const float4*)Hin;
#pragma unroll 8
        for (int b = 0; b < 64; b++)
            sH4[b * SROW + tid] = __ldcg(&Hin4[(size_t)(b0 + b) * 256 + kOff4 + tid]);
        __syncthreads();

        float acc[4][2];
#pragma unroll
        for (int i = 0; i < 4; i++) { acc[i][0] = 0.f; acc[i][1] = 0.f; }

        const float4* w0p = &sW4[(ty * 2) * SROW];
        const float4* w1p = &sW4[(ty * 2 + 1) * SROW];
#pragma unroll 2
        for (int kq = 0; kq < 128; kq++) {
            float4 w0 = w0p[kq];
            float4 w1 = w1p[kq];
#pragma unroll
            for (int i = 0; i < 4; i++) {
                float4 a = sH4[(tx + 16 * i) * SROW + kq];
                acc[i][0] += a.x * w0.x; acc[i][0] += a.y * w0.y;
                acc[i][0] += a.z * w0.z; acc[i][0] += a.w * w0.w;
                acc[i][1] += a.x * w1.x; acc[i][1] += a.y * w1.y;
                acc[i][1] += a.z * w1.z; acc[i][1] += a.w * w1.w;
            }
        }

        const float* Pt = P + (size_t)t * BB * NH;
        const int n = nBase + ty * 2;
#pragma unroll
        for (int i = 0; i < 4; i++) {
            int b = b0 + tx + 16 * i;
            float2 p = *(const float2*)&Pt[(size_t)b * NH + n];
            float2 o;
            o.x = fmaxf(acc[i][0] + p.x, 0.f);
            o.y = fmaxf(acc[i][1] + p.y, 0.f);
            __stcg((float2*)&Hout[(size_t)b * NH + n], o);
        }

        __syncthreads();
        __threadfence();
        if (tid == 0) {
            atomicAdd(&ctr[t], 1);
            while (((volatile int*)ctr)[t] < NCTA) __nanosleep(64);
        }
        __syncthreads();
        __threadfence();
    }
}

// ---------------- BatchNorm1d (training, biased var) + ReLU ----------------
__global__ void bn_relu(const float* __restrict__ V, const float* __restrict__ gw,
                        const float* __restrict__ bw, float* __restrict__ Y, int cols)
{
    int c = blockIdx.x;
    int t = threadIdx.x;
    float v = V[(size_t)t * cols + c];
    float s = v, ss = v * v;
#pragma unroll
    for (int o = 16; o > 0; o >>= 1) {
        s  += __shfl_down_sync(0xffffffffu, s,  o);
        ss += __shfl_down_sync(0xffffffffu, ss, o);
    }
    __shared__ float rs[4], rq[4];
    if ((t & 31) == 0) { rs[t >> 5] = s; rq[t >> 5] = ss; }
    __syncthreads();
    float S = rs[0] + rs[1] + rs[2] + rs[3];
    float Q = rq[0] + rq[1] + rq[2] + rq[3];
    float mean = S * (1.f / BB);
    float var  = Q * (1.f / BB) - mean * mean;
    float y = (v - mean) * rsqrtf(var + EPSF) * gw[c] + bw[c];
    Y[(size_t)t * cols + c] = fmaxf(y, 0.f);
}

// ---------------- launch ----------------
extern "C" void kernel_launch(void* const* d_in, const int* in_sizes, int n_in,
                              void* d_out, int out_size)
{
    (void)in_sizes; (void)n_in; (void)out_size;
    const float* x     = (const float*)d_in[0];
    const float* h0    = (const float*)d_in[1];
    const float* W_ih0 = (const float*)d_in[2];
    const float* W_hh0 = (const float*)d_in[3];
    const float* b_ih0 = (const float*)d_in[4];
    const float* b_hh0 = (const float*)d_in[5];
    const float* W_ih1 = (const float*)d_in[6];
    const float* W_hh1 = (const float*)d_in[7];
    const float* b_ih1 = (const float*)d_in[8];
    const float* b_hh1 = (const float*)d_in[9];
    const float* bn1_g = (const float*)d_in[10];
    const float* bn1_b = (const float*)d_in[11];
    const float* fc1_W = (const float*)d_in[12];
    const float* fc1_b = (const float*)d_in[13];
    const float* bn2_g = (const float*)d_in[14];
    const float* bn2_b = (const float*)d_in[15];
    const float* fc2_W = (const float*)d_in[16];
    const float* fc2_b = (const float*)d_in[17];
    float* out = (float*)d_out;

    float *P, *H0p, *hi0, *hi1, *h1a, *h1b, *bs0, *bs1, *y1, *z;
    int *c0, *c1;
    cudaGetSymbolAddress((void**)&P,   g_P);
    cudaGetSymbolAddress((void**)&H0p, g_H0buf);
    cudaGetSymbolAddress((void**)&hi0, g_hi0);
    cudaGetSymbolAddress((void**)&hi1, g_hi1);
    cudaGetSymbolAddress((void**)&h1a, g_h1a);
    cudaGetSymbolAddress((void**)&h1b, g_h1b);
    cudaGetSymbolAddress((void**)&bs0, g_bias0);
    cudaGetSymbolAddress((void**)&bs1, g_bias1);
    cudaGetSymbolAddress((void**)&y1,  g_y1);
    cudaGetSymbolAddress((void**)&z,   g_z);
    cudaGetSymbolAddress((void**)&c0,  g_ctr0);
    cudaGetSymbolAddress((void**)&c1,  g_ctr1);

    cudaFuncSetAttribute(rnn_layer<1>, cudaFuncAttributeMaxDynamicSharedMemorySize, RNN_SMEM);
    cudaFuncSetAttribute(rnn_layer<0>, cudaFuncAttributeMaxDynamicSharedMemorySize, RNN_SMEM);

    // 0) biases + initial hidden + barrier counters
    setup_kernel<<<256, 256>>>(h0, b_ih0, b_hh0, b_ih1, b_hh1);

    // 1) P0 = x @ Wih0^T + biases   (34.4 GMAC)
    gemm_big<1><<<dim3(NH / 128, M_BIG / 128), 256>>>(x, W_ih0, bs0, P, M_BIG, NH, IND);

    // 2) layer-0 recurrence (68.7 GMAC, all timesteps stored)
    rnn_layer<1><<<NCTA, 128, RNN_SMEM>>>(P, hi0, W_hh0, H0p, nullptr, nullptr, c0);

    // 3) P1 = H0 @ Wih1^T + biases  (137.4 GMAC)
    gemm_big<0><<<dim3(NH / 128, M_BIG / 128), 256>>>(H0p, W_ih1, bs1, P, M_BIG, NH, NH);

    // 4) layer-1 recurrence; final state lands in h1b (t=1023 odd)
    rnn_layer<0><<<NCTA, 128, RNN_SMEM>>>(P, hi1, W_hh1, nullptr, h1a, h1b, c1);

    // 5) head
    bn_relu<<<NH, 128>>>(h1b, bn1_g, bn1_b, y1, NH);
    gemm_bias<0><<<dim3(FC1N / 64, BB / 64), 256>>>(y1, fc1_W, fc1_b, z, BB, FC1N, NH);
    bn_relu<<<FC1N, 128>>>(z, bn2_g, bn2_b, z, FC1N);
    gemm_bias<2><<<dim3(OUTN / 64, BB / 64), 256>>>(z, fc2_W, fc2_b, out, BB, OUTN, FC1N);
}